// round 15
// baseline (speedup 1.0000x reference)
#include <cuda_runtime.h>
#include <math.h>
#include <stdint.h>

// Problem constants
#define BB   8
#define NN   8192
#define SS   2048
#define DD   256
#define MM   65536      // BB*NN
#define H0   256
#define H1   128
#define K0   512        // 2*DD
#define BNEPS 1e-5f

// ---------------------------------------------------------------------------
// Scratch
// ---------------------------------------------------------------------------
__device__ float  g_y0 [(size_t)MM * H0];   // layer0 pre-BN output (fp32)
__device__ float  g_w0t[H0 * K0];           // W0 as tf32 bits
__device__ float  g_w1t[H1 * H0];           // W1 as tf32 bits
__device__ int    g_idx[MM * 3];
__device__ float  g_w  [MM * 3];
__device__ double g_sum0[H0], g_ss0[H0], g_sum1[H1], g_ss1[H1];

// ---------------------------------------------------------------------------
// Portable PTX helpers
// ---------------------------------------------------------------------------
__device__ __forceinline__ uint32_t smem_u32(const void* p) {
    uint32_t a;
    asm("{ .reg .u64 t; cvta.to.shared.u64 t, %1; cvt.u32.u64 %0, t; }" : "=r"(a) : "l"(p));
    return a;
}

#define CP_ASYNC16(dst, src) \
    asm volatile("cp.async.cg.shared.global [%0], [%1], 16;" :: "r"(dst), "l"(src) : "memory")
#define CP_COMMIT() asm volatile("cp.async.commit_group;" ::: "memory")
#define CP_WAIT(n)  asm volatile("cp.async.wait_group %0;" :: "n"(n) : "memory")

__device__ __forceinline__ float f2tf32f(float x) {
    uint32_t r;
    asm("cvt.rna.tf32.f32 %0, %1;" : "=r"(r) : "f"(x));
    return __uint_as_float(r);
}

__device__ __forceinline__ void mma_tf32_16x8x8(float* c, const uint32_t* a,
                                                const uint32_t* b) {
    asm volatile(
        "mma.sync.aligned.m16n8k8.row.col.f32.tf32.tf32.f32 "
        "{%0,%1,%2,%3}, {%4,%5,%6,%7}, {%8,%9}, {%0,%1,%2,%3};"
        : "+f"(c[0]), "+f"(c[1]), "+f"(c[2]), "+f"(c[3])
        : "r"(a[0]), "r"(a[1]), "r"(a[2]), "r"(a[3]), "r"(b[0]), "r"(b[1]));
}

// ---------------------------------------------------------------------------
// prep: zero stats (block 0) + convert W0/W1 to tf32 bits
// ---------------------------------------------------------------------------
__global__ void prep_kernel(const float* __restrict__ W0,
                            const float* __restrict__ W1) {
    int i = blockIdx.x * blockDim.x + threadIdx.x;
    if (blockIdx.x == 0) {
        int t = threadIdx.x;
        if (t < H0) { g_sum0[t] = 0.0; g_ss0[t] = 0.0; }
        if (t < H1) { g_sum1[t] = 0.0; g_ss1[t] = 0.0; }
    }
    if (i < H0 * K0) g_w0t[i] = f2tf32f(W0[i]);
    if (i < H1 * H0) g_w1t[i] = f2tf32f(W1[i]);
}

// KNN: 128 threads/block, each thread handles 2 query points (tid, tid+128).
__global__ void knn_kernel(const float* __restrict__ xyz1,
                           const float* __restrict__ xyz2,
                           const float* __restrict__ rel_w,
                           const float* __restrict__ rel_b) {
    __shared__ float4 sh[SS];
    const int b = blockIdx.y;
    const float* x2 = xyz2 + (size_t)b * SS * 3;
    for (int s = threadIdx.x; s < SS; s += 128) {
        float x = x2[s * 3 + 0], y = x2[s * 3 + 1], z = x2[s * 3 + 2];
        sh[s] = make_float4(x, y, z, x * x + y * y + z * z);
    }
    __syncthreads();

    const int nA = blockIdx.x * 256 + threadIdx.x;
    const int gA = b * NN + nA;
    const int gB = gA + 128;

    const float ax = xyz1[(size_t)gA * 3 + 0];
    const float ay = xyz1[(size_t)gA * 3 + 1];
    const float az = xyz1[(size_t)gA * 3 + 2];
    const float an = ax * ax + ay * ay + az * az;
    const float bx = xyz1[(size_t)gB * 3 + 0];
    const float by = xyz1[(size_t)gB * 3 + 1];
    const float bz = xyz1[(size_t)gB * 3 + 2];
    const float bn = bx * bx + by * by + bz * bz;

    float ad0 = 3.4e38f, ad1 = 3.4e38f, ad2 = 3.4e38f;
    int   ai0 = 0, ai1 = 0, ai2 = 0;
    float bd0 = 3.4e38f, bd1 = 3.4e38f, bd2 = 3.4e38f;
    int   bi0 = 0, bi1 = 0, bi2 = 0;

    #pragma unroll 4
    for (int s = 0; s < SS; s++) {
        float4 p = sh[s];
        float da = (an + p.w) - 2.0f * (ax * p.x + ay * p.y + az * p.z);
        float db = (bn + p.w) - 2.0f * (bx * p.x + by * p.y + bz * p.z);
        if (da < ad2) {
            if (da < ad1) {
                ad2 = ad1; ai2 = ai1;
                if (da < ad0) { ad1 = ad0; ai1 = ai0; ad0 = da; ai0 = s; }
                else          { ad1 = da;  ai1 = s; }
            } else { ad2 = da; ai2 = s; }
        }
        if (db < bd2) {
            if (db < bd1) {
                bd2 = bd1; bi2 = bi1;
                if (db < bd0) { bd1 = bd0; bi1 = bi0; bd0 = db; bi0 = s; }
                else          { bd1 = db;  bi1 = s; }
            } else { bd2 = db; bi2 = s; }
        }
    }

    const float rw0 = rel_w[0], rw1 = rel_w[1], rw2 = rel_w[2], rw3 = rel_w[3];
    const float rb  = rel_b[0];
    {
        int   is[3] = { ai0, ai1, ai2 };
        float ds[3] = { ad0, ad1, ad2 };
        #pragma unroll
        for (int k = 0; k < 3; k++) {
            float4 p = sh[is[k]];
            float ox = ax - p.x, oy = ay - p.y, oz = az - p.z;
            float zl = ds[k] * rw0 + ox * rw1 + oy * rw2 + oz * rw3 + rb;
            float w = 1.0f / (1.0f + expf(-zl));
            g_idx[gA * 3 + k] = is[k];
            g_w[gA * 3 + k]   = w * (1.0f / 3.0f);
        }
    }
    {
        int   is[3] = { bi0, bi1, bi2 };
        float ds[3] = { bd0, bd1, bd2 };
        #pragma unroll
        for (int k = 0; k < 3; k++) {
            float4 p = sh[is[k]];
            float ox = bx - p.x, oy = by - p.y, oz = bz - p.z;
            float zl = ds[k] * rw0 + ox * rw1 + oy * rw2 + oz * rw3 + rb;
            float w = 1.0f / (1.0f + expf(-zl));
            g_idx[gB * 3 + k] = is[k];
            g_w[gB * 3 + k]   = w * (1.0f / 3.0f);
        }
    }
}

// ---------------------------------------------------------------------------
// GEMM0 with fused interp/concat on A. Tile 64x256, 256 threads, 2 CTAs/SM.
// R9 configuration (best measured: 150.7us). LDT=36, 2-stage, LDS.32 frags.
// ---------------------------------------------------------------------------
__global__ __launch_bounds__(256, 2)
void gemm0_kernel(const float* __restrict__ points1,
                  const float* __restrict__ points2,
                  const float* __restrict__ Bw,
                  const float* __restrict__ bias, float* __restrict__ C,
                  double* __restrict__ Sum, double* __restrict__ Ss) {
    constexpr int KT    = K0;             // 512
    constexpr int NT    = H0;             // 256
    constexpr int TM    = 64;
    constexpr int NC    = KT / 32;        // 16
    constexpr int LDT   = 36;
    constexpr int STAGE = (TM + NT) * LDT;

    extern __shared__ float sm[];
    const uint32_t smb = smem_u32(sm);

    const int tid    = threadIdx.x;
    const int wid    = tid >> 5;
    const int lane   = tid & 31;
    const int g      = lane >> 2;
    const int tg     = lane & 3;
    const int warp_m = wid >> 2;          // 0..1
    const int warp_n = wid & 3;           // 0..3
    const size_t bm  = (size_t)blockIdx.x * TM;

    // A staging: row lr (0..63), col group lq*8
    const int lr = tid >> 2;
    const int lq = tid & 3;
    const int gn = (int)bm + lr;
    const float* p2b = points2 + (size_t)(gn >> 13) * SS * DD;
    const int   j0 = g_idx[gn * 3 + 0], j1 = g_idx[gn * 3 + 1], j2 = g_idx[gn * 3 + 2];
    const float w0 = g_w[gn * 3 + 0],  w1 = g_w[gn * 3 + 1],  w2 = g_w[gn * 3 + 2];
    const float* r0 = p2b + (size_t)j0 * DD;
    const float* r1 = p2b + (size_t)j1 * DD;
    const float* r2 = p2b + (size_t)j2 * DD;
    const float* q  = points1 + (size_t)gn * DD;

    float acc[2][8][4];
    #pragma unroll
    for (int mt = 0; mt < 2; mt++)
        #pragma unroll
        for (int nt = 0; nt < 8; nt++)
            #pragma unroll
            for (int i = 0; i < 4; i++) acc[mt][nt][i] = 0.0f;

    auto load_a_regs = [&](int kt, float4* av) {
        if (kt < 8) {
            const float* P = q + kt * 32 + lq * 8;
            av[0] = *(const float4*)P;
            av[1] = *(const float4*)(P + 4);
        } else {
            const int cc = (kt - 8) * 32 + lq * 8;
            av[0] = *(const float4*)(r0 + cc);
            av[1] = *(const float4*)(r0 + cc + 4);
            av[2] = *(const float4*)(r1 + cc);
            av[3] = *(const float4*)(r1 + cc + 4);
            av[4] = *(const float4*)(r2 + cc);
            av[5] = *(const float4*)(r2 + cc + 4);
        }
    };
    auto store_a = [&](int kt, int s, const float4* av) {
        float* dst = sm + s * STAGE + lr * LDT + lq * 8;
        if (kt < 8) {
            #pragma unroll
            for (int i = 0; i < 2; i++) {
                float4 v;
                v.x = f2tf32f(av[i].x); v.y = f2tf32f(av[i].y);
                v.z = f2tf32f(av[i].z); v.w = f2tf32f(av[i].w);
                *(float4*)(dst + 4 * i) = v;
            }
        } else {
            #pragma unroll
            for (int i = 0; i < 2; i++) {
                float4 a = av[i], b = av[2 + i], c = av[4 + i];
                float4 v;
                v.x = f2tf32f(fmaf(a.x, w0, fmaf(b.x, w1, c.x * w2)));
                v.y = f2tf32f(fmaf(a.y, w0, fmaf(b.y, w1, c.y * w2)));
                v.z = f2tf32f(fmaf(a.z, w0, fmaf(b.z, w1, c.z * w2)));
                v.w = f2tf32f(fmaf(a.w, w0, fmaf(b.w, w1, c.w * w2)));
                *(float4*)(dst + 4 * i) = v;
            }
        }
    };
    auto load_b_stage = [&](int kt, int s) {
        const float* Bg = Bw + kt * 32;
        const uint32_t base = smb + (uint32_t)(s * STAGE + TM * LDT) * 4u;
        #pragma unroll
        for (int i = 0; i < 8; i++) {
            int id = i * 256 + tid;
            int r = id >> 3, kk = (id & 7) * 4;
            CP_ASYNC16(base + (r * LDT + kk) * 4, Bg + (size_t)r * KT + kk);
        }
        CP_COMMIT();
    };

    // prologue: stage 0
    {
        float4 av[6];
        load_a_regs(0, av);
        load_b_stage(0, 0);
        store_a(0, 0, av);
    }

    for (int kt = 0; kt < NC; kt++) {
        CP_WAIT(0);          // B(kt) landed
        __syncthreads();     // stage kt visible; buf (kt+1)&1 free

        float4 av[6];
        if (kt + 1 < NC) {
            load_a_regs(kt + 1, av);          // LDG overlaps compute(kt)
            load_b_stage(kt + 1, (kt + 1) & 1);
        }

        const uint32_t* as = (const uint32_t*)sm + (kt & 1) * STAGE + (warp_m * 32) * LDT;
        const uint32_t* bs = (const uint32_t*)sm + (kt & 1) * STAGE + TM * LDT
                           + (warp_n * 64) * LDT;

        #pragma unroll
        for (int kc = 0; kc < 4; kc++) {
            uint32_t a[2][4];
            #pragma unroll
            for (int mt = 0; mt < 2; mt++) {
                int base = (mt * 16 + g) * LDT + kc * 8 + tg;
                a[mt][0] = as[base];
                a[mt][1] = as[base + 8 * LDT];
                a[mt][2] = as[base + 4];
                a[mt][3] = as[base + 8 * LDT + 4];
            }
            #pragma unroll
            for (int nt = 0; nt < 8; nt++) {
                int bb = (nt * 8 + g) * LDT + kc * 8 + tg;
                uint32_t b[2] = { bs[bb], bs[bb + 4] };
                mma_tf32_16x8x8(acc[0][nt], a[0], b);
                mma_tf32_16x8x8(acc[1][nt], a[1], b);
            }
        }

        if (kt + 1 < NC) store_a(kt + 1, (kt + 1) & 1, av);
    }

    // stats partials (smem reuse)
    __syncthreads();
    if (tid < NT) { sm[tid] = 0.0f; sm[NT + tid] = 0.0f; }
    __syncthreads();

    #pragma unroll
    for (int nt = 0; nt < 8; nt++) {
        int col = warp_n * 64 + nt * 8 + 2 * tg;
        float bi0 = __ldg(&bias[col]), bi1 = __ldg(&bias[col + 1]);
        float s0 = 0.f, s1 = 0.f, q0 = 0.f, q1 = 0.f;
        #pragma unroll
        for (int mt = 0; mt < 2; mt++) {
            size_t r = bm + warp_m * 32 + mt * 16 + g;
            float v0x = acc[mt][nt][0] + bi0, v0y = acc[mt][nt][1] + bi1;
            float v1x = acc[mt][nt][2] + bi0, v1y = acc[mt][nt][3] + bi1;
            *(float2*)(C + r * NT + col)       = make_float2(v0x, v0y);
            *(float2*)(C + (r + 8) * NT + col) = make_float2(v1x, v1y);
            s0 += v0x + v1x;  s1 += v0y + v1y;
            q0 += v0x * v0x + v1x * v1x;
            q1 += v0y * v0y + v1y * v1y;
        }
        #pragma unroll
        for (int d = 4; d < 32; d <<= 1) {
            s0 += __shfl_xor_sync(0xffffffffu, s0, d);
            s1 += __shfl_xor_sync(0xffffffffu, s1, d);
            q0 += __shfl_xor_sync(0xffffffffu, q0, d);
            q1 += __shfl_xor_sync(0xffffffffu, q1, d);
        }
        if (lane < 4) {
            int c = warp_n * 64 + nt * 8 + 2 * lane;
            atomicAdd(&sm[c],          s0);
            atomicAdd(&sm[c + 1],      s1);
            atomicAdd(&sm[NT + c],     q0);
            atomicAdd(&sm[NT + c + 1], q1);
        }
    }
    __syncthreads();
    if (tid < NT) {
        atomicAdd(&Sum[tid], (double)sm[tid]);
        atomicAdd(&Ss[tid],  (double)sm[NT + tid]);
    }
}

// ---------------------------------------------------------------------------
// GEMM1: out = relu(s0*Y0 + t0) @ W1^T + b1, fused BN on A + fused stats.
// BN0 finalize is computed per-CTA into static smem (identical formula ->
// identical values), removing the separate finalize launch.
// 128x128 tile, 3-stage pipeline (CP_WAIT(1)), 2 CTAs/SM.
// ---------------------------------------------------------------------------
__global__ __launch_bounds__(256, 2)
void gemm1_kernel(const float* __restrict__ A, const float* __restrict__ Bw,
                  const float* __restrict__ bias,
                  const double* __restrict__ Sum0, const double* __restrict__ Ss0,
                  const float* __restrict__ gamma0, const float* __restrict__ beta0,
                  float* __restrict__ C,
                  double* __restrict__ Sum, double* __restrict__ Ss) {
    constexpr int KT    = H0;             // 256
    constexpr int NT    = H1;             // 128
    constexpr int NC    = KT / 32;        // 8
    constexpr int LDT   = 36;
    constexpr int STAGE = 2 * 128 * LDT;  // A rows then B rows

    extern __shared__ float sm[];
    __shared__ float s_sc[H0], s_shf[H0];
    const uint32_t smb = smem_u32(sm);

    const int tid    = threadIdx.x;
    const int wid    = tid >> 5;
    const int lane   = tid & 31;
    const int g      = lane >> 2;
    const int tg     = lane & 3;
    const int warp_m = wid >> 1;
    const int warp_n = wid & 1;
    const size_t bm  = (size_t)blockIdx.x * 128;

    const int lr = tid >> 1;
    const int lk = (tid & 1) * 16;

    // per-CTA BN0 finalize (identical formula to the old finalize_kernel)
    {
        double mean = Sum0[tid] * (1.0 / (double)MM);
        double var  = Ss0[tid]  * (1.0 / (double)MM) - mean * mean;
        float s = gamma0[tid] * rsqrtf((float)var + BNEPS);
        s_sc[tid]  = s;
        s_shf[tid] = beta0[tid] - (float)mean * s;
    }

    float acc[2][8][4];
    #pragma unroll
    for (int mt = 0; mt < 2; mt++)
        #pragma unroll
        for (int nt = 0; nt < 8; nt++)
            #pragma unroll
            for (int i = 0; i < 4; i++) acc[mt][nt][i] = 0.0f;

    auto load_a_regs = [&](int kt, float4* av) {
        const float* Ag = A + (size_t)(bm + lr) * KT + kt * 32 + lk;
        #pragma unroll
        for (int i = 0; i < 4; i++) av[i] = *(const float4*)(Ag + 4 * i);
    };
    auto store_a = [&](int kt, int s, const float4* av) {
        const int c0 = kt * 32 + lk;
        float* dst = sm + s * STAGE + lr * LDT + lk;
        #pragma unroll
        for (int i = 0; i < 4; i++) {
            float4 s4 = *(const float4*)(s_sc  + c0 + 4 * i);
            float4 t4 = *(const float4*)(s_shf + c0 + 4 * i);
            float4 v;
            v.x = f2tf32f(fmaxf(0.0f, fmaf(av[i].x, s4.x, t4.x)));
            v.y = f2tf32f(fmaxf(0.0f, fmaf(av[i].y, s4.y, t4.y)));
            v.z = f2tf32f(fmaxf(0.0f, fmaf(av[i].z, s4.z, t4.z)));
            v.w = f2tf32f(fmaxf(0.0f, fmaf(av[i].w, s4.w, t4.w)));
            *(float4*)(dst + 4 * i) = v;
        }
    };
    auto load_b_stage = [&](int kt, int s) {
        const float* Bg = Bw + kt * 32;
        const uint32_t base = smb + (uint32_t)(s * STAGE + 128 * LDT) * 4u;
        #pragma unroll
        for (int i = 0; i < 4; i++) {
            int id = i * 256 + tid;
            int r = id >> 3, kk = (id & 7) * 4;
            CP_ASYNC16(base + (r * LDT + kk) * 4, Bg + (size_t)r * KT + kk);
        }
        CP_COMMIT();
    };

    // prologue: stages 0 and 1 (store_a only after s_sc/s_shf are published)
    {
        float4 av0[4], av1[4];
        load_b_stage(0, 0);
        load_a_regs(0, av0);
        load_b_stage(1, 1);
        load_a_regs(1, av1);
        __syncthreads();               // s_sc/s_shf visible to all threads
        store_a(0, 0, av0);
        store_a(1, 1, av1);
    }

    for (int kt = 0; kt < NC; kt++) {
        if (kt + 1 < NC) { CP_WAIT(1); } else { CP_WAIT(0); }
        __syncthreads();     // stage kt%3 visible; stage (kt+2)%3 free

        float4 av[4];
        if (kt + 2 < NC) {
            load_a_regs(kt + 2, av);
            load_b_stage(kt + 2, (kt + 2) % 3);
        }

        const uint32_t* as = (const uint32_t*)sm + (kt % 3) * STAGE + (warp_m * 32) * LDT;
        const uint32_t* bs = (const uint32_t*)sm + (kt % 3) * STAGE + 128 * LDT
                           + (warp_n * 64) * LDT;

        #pragma unroll
        for (int kc = 0; kc < 4; kc++) {
            uint32_t a[2][4];
            #pragma unroll
            for (int mt = 0; mt < 2; mt++) {
                int base = (mt * 16 + g) * LDT + kc * 8 + tg;
                a[mt][0] = as[base];
                a[mt][1] = as[base + 8 * LDT];
                a[mt][2] = as[base + 4];
                a[mt][3] = as[base + 8 * LDT + 4];
            }
            #pragma unroll
            for (int nt = 0; nt < 8; nt++) {
                int bb = (nt * 8 + g) * LDT + kc * 8 + tg;
                uint32_t b[2] = { bs[bb], bs[bb + 4] };
                mma_tf32_16x8x8(acc[0][nt], a[0], b);
                mma_tf32_16x8x8(acc[1][nt], a[1], b);
            }
        }

        if (kt + 2 < NC) store_a(kt + 2, (kt + 2) % 3, av);
    }

    __syncthreads();
    if (tid < NT) { sm[tid] = 0.0f; sm[NT + tid] = 0.0f; }
    __syncthreads();

    #pragma unroll
    for (int nt = 0; nt < 8; nt++) {
        int col = warp_n * 64 + nt * 8 + 2 * tg;
        float bi0 = __ldg(&bias[col]), bi1 = __ldg(&bias[col + 1]);
        float s0 = 0.f, s1 = 0.f, q0 = 0.f, q1 = 0.f;
        #pragma unroll
        for (int mt = 0; mt < 2; mt++) {
            size_t r = bm + warp_m * 32 + mt * 16 + g;
            float v0x = acc[mt][nt][0] + bi0, v0y = acc[mt][nt][1] + bi1;
            float v1x = acc[mt][nt][2] + bi0, v1y = acc[mt][nt][3] + bi1;
            *(float2*)(C + r * NT + col)       = make_float2(v0x, v0y);
            *(float2*)(C + (r + 8) * NT + col) = make_float2(v1x, v1y);
            s0 += v0x + v1x;  s1 += v0y + v1y;
            q0 += v0x * v0x + v1x * v1x;
            q1 += v0y * v0y + v1y * v1y;
        }
        #pragma unroll
        for (int d = 4; d < 32; d <<= 1) {
            s0 += __shfl_xor_sync(0xffffffffu, s0, d);
            s1 += __shfl_xor_sync(0xffffffffu, s1, d);
            q0 += __shfl_xor_sync(0xffffffffu, q0, d);
            q1 += __shfl_xor_sync(0xffffffffu, q1, d);
        }
        if (lane < 4) {
            int c = warp_n * 64 + nt * 8 + 2 * lane;
            atomicAdd(&sm[c],          s0);
            atomicAdd(&sm[c + 1],      s1);
            atomicAdd(&sm[NT + c],     q0);
            atomicAdd(&sm[NT + c + 1], q1);
        }
    }
    __syncthreads();
    if (tid < NT) {
        atomicAdd(&Sum[tid], (double)sm[tid]);
        atomicAdd(&Ss[tid],  (double)sm[NT + tid]);
    }
}

// ---------------------------------------------------------------------------
// act: per-block BN1 finalize (identical formula) + BN+ReLU in place on d_out.
// ---------------------------------------------------------------------------
__global__ void act_kernel(float* __restrict__ Y,
                           const double* __restrict__ Sum1,
                           const double* __restrict__ Ss1,
                           const float* __restrict__ gamma1,
                           const float* __restrict__ beta1) {
    __shared__ float s_sc[H1], s_shf[H1];
    int t = threadIdx.x;
    if (t < H1) {
        double mean = Sum1[t] * (1.0 / (double)MM);
        double var  = Ss1[t]  * (1.0 / (double)MM) - mean * mean;
        float s = gamma1[t] * rsqrtf((float)var + BNEPS);
        s_sc[t]  = s;
        s_shf[t] = beta1[t] - (float)mean * s;
    }
    __syncthreads();

    int i = blockIdx.x * blockDim.x + threadIdx.x;      // float4 index
    float4 v = ((float4*)Y)[i];
    const float4 s4 = *(const float4*)(s_sc  + (i & 31) * 4);
    const float4 t4 = *(const float4*)(s_shf + (i & 31) * 4);
    v.x = fmaxf(0.0f, fmaf(v.x, s4.x, t4.x));
    v.y = fmaxf(0.0f, fmaf(v.y, s4.y, t4.y));
    v.z = fmaxf(0.0f, fmaf(v.z, s4.z, t4.z));
    v.w = fmaxf(0.0f, fmaf(v.w, s4.w, t4.w));
    ((float4*)Y)[i] = v;
}

// ---------------------------------------------------------------------------
// Launch sequence: prep(1), knn(2), gemm0(3), gemm1(4 <- profiled), act(5)
// ---------------------------------------------------------------------------
extern "C" void kernel_launch(void* const* d_in, const int* in_sizes, int n_in,
                              void* d_out, int out_size) {
    const float* xyz1    = (const float*)d_in[0];
    const float* xyz2    = (const float*)d_in[1];
    const float* points1 = (const float*)d_in[2];
    const float* points2 = (const float*)d_in[3];
    const float* rel_w   = (const float*)d_in[4];
    const float* rel_b   = (const float*)d_in[5];
    const float* W0      = (const float*)d_in[6];
    const float* b0      = (const float*)d_in[7];
    const float* g0      = (const float*)d_in[8];
    const float* be0     = (const float*)d_in[9];
    const float* W1      = (const float*)d_in[10];
    const float* b1      = (const float*)d_in[11];
    const float* g1      = (const float*)d_in[12];
    const float* be1     = (const float*)d_in[13];
    float* out = (float*)d_out;

    float *p_y0, *p_w0t, *p_w1t;
    double *p_sum0, *p_ss0, *p_sum1, *p_ss1;
    cudaGetSymbolAddress((void**)&p_y0,   g_y0);
    cudaGetSymbolAddress((void**)&p_w0t,  g_w0t);
    cudaGetSymbolAddress((void**)&p_w1t,  g_w1t);
    cudaGetSymbolAddress((void**)&p_sum0, g_sum0);
    cudaGetSymbolAddress((void**)&p_ss0,  g_ss0);
    cudaGetSymbolAddress((void**)&p_sum1, g_sum1);
    cudaGetSymbolAddress((void**)&p_ss1,  g_ss1);

    const int smem0 = (64 + H0) * 36 * 4 * 2;     // 92160 B (2 stages)
    const int smem1 = 3 * 2 * 128 * 36 * 4;       // 110592 B (3 stages)
    cudaFuncSetAttribute(gemm0_kernel,
                         cudaFuncAttributeMaxDynamicSharedMemorySize, smem0);
    cudaFuncSetAttribute(gemm1_kernel,
                         cudaFuncAttributeMaxDynamicSharedMemorySize, smem1);

    prep_kernel<<<(H0 * K0 + 255) / 256, 256>>>(W0, W1);
    knn_kernel<<<dim3(NN / 256, BB), 128>>>(xyz1, xyz2, rel_w, rel_b);

    gemm0_kernel<<<MM / 64, 256, smem0>>>(points1, points2, p_w0t, b0,
                                          p_y0, p_sum0, p_ss0);

    gemm1_kernel<<<MM / 128, 256, smem1>>>(p_y0, p_w1t, b1,
                                           p_sum0, p_ss0, g0, be0,
                                           out, p_sum1, p_ss1);

    act_kernel<<<(MM * H1 / 4) / 256, 256>>>(out, p_sum1, p_ss1, g1, be1);
}

// round 16
// speedup vs baseline: 1.1275x; 1.1275x over previous
#include <cuda_runtime.h>
#include <math.h>
#include <stdint.h>

// Problem constants
#define BB   8
#define NN   8192
#define SS   2048
#define DD   256
#define MM   65536      // BB*NN
#define H0   256
#define H1   128
#define K0   512        // 2*DD
#define BNEPS 1e-5f

// ---------------------------------------------------------------------------
// Scratch
// ---------------------------------------------------------------------------
__device__ float  g_y0 [(size_t)MM * H0];   // layer0 pre-BN output (fp32)
__device__ float  g_w0t[H0 * K0];           // W0 as tf32 bits
__device__ float  g_w1t[H1 * H0];           // W1 as tf32 bits
__device__ int    g_idx[MM * 3];
__device__ float  g_w  [MM * 3];
__device__ double g_sum0[H0], g_ss0[H0], g_sum1[H1], g_ss1[H1];

// ---------------------------------------------------------------------------
// Portable PTX helpers
// ---------------------------------------------------------------------------
__device__ __forceinline__ uint32_t smem_u32(const void* p) {
    uint32_t a;
    asm("{ .reg .u64 t; cvta.to.shared.u64 t, %1; cvt.u32.u64 %0, t; }" : "=r"(a) : "l"(p));
    return a;
}

#define CP_ASYNC16(dst, src) \
    asm volatile("cp.async.cg.shared.global [%0], [%1], 16;" :: "r"(dst), "l"(src) : "memory")
#define CP_COMMIT() asm volatile("cp.async.commit_group;" ::: "memory")
#define CP_WAIT(n)  asm volatile("cp.async.wait_group %0;" :: "n"(n) : "memory")

__device__ __forceinline__ float f2tf32f(float x) {
    uint32_t r;
    asm("cvt.rna.tf32.f32 %0, %1;" : "=r"(r) : "f"(x));
    return __uint_as_float(r);
}

__device__ __forceinline__ void mma_tf32_16x8x8(float* c, const uint32_t* a,
                                                const uint32_t* b) {
    asm volatile(
        "mma.sync.aligned.m16n8k8.row.col.f32.tf32.tf32.f32 "
        "{%0,%1,%2,%3}, {%4,%5,%6,%7}, {%8,%9}, {%0,%1,%2,%3};"
        : "+f"(c[0]), "+f"(c[1]), "+f"(c[2]), "+f"(c[3])
        : "r"(a[0]), "r"(a[1]), "r"(a[2]), "r"(a[3]), "r"(b[0]), "r"(b[1]));
}

// ---------------------------------------------------------------------------
// prep: zero stats (block 0) + convert W0/W1 to tf32 bits
// ---------------------------------------------------------------------------
__global__ void prep_kernel(const float* __restrict__ W0,
                            const float* __restrict__ W1) {
    int i = blockIdx.x * blockDim.x + threadIdx.x;
    if (blockIdx.x == 0) {
        int t = threadIdx.x;
        if (t < H0) { g_sum0[t] = 0.0; g_ss0[t] = 0.0; }
        if (t < H1) { g_sum1[t] = 0.0; g_ss1[t] = 0.0; }
    }
    if (i < H0 * K0) g_w0t[i] = f2tf32f(W0[i]);
    if (i < H1 * H0) g_w1t[i] = f2tf32f(W1[i]);
}

// ---------------------------------------------------------------------------
// KNN: 1 query per thread, 128 threads/block, grid (NN/128, BB) = 512 blocks.
// 2048 warps total (vs 1024 in the 2-query version): the serial compare
// chain is latency-bound, so more resident warps -> more overlap.
// Per-query arithmetic and scan order identical to all prior versions.
// ---------------------------------------------------------------------------
__global__ void knn_kernel(const float* __restrict__ xyz1,
                           const float* __restrict__ xyz2,
                           const float* __restrict__ rel_w,
                           const float* __restrict__ rel_b) {
    __shared__ float4 sh[SS];
    const int b = blockIdx.y;
    const float* x2 = xyz2 + (size_t)b * SS * 3;
    for (int s = threadIdx.x; s < SS; s += 128) {
        float x = x2[s * 3 + 0], y = x2[s * 3 + 1], z = x2[s * 3 + 2];
        sh[s] = make_float4(x, y, z, x * x + y * y + z * z);
    }
    __syncthreads();

    const int n  = blockIdx.x * 128 + threadIdx.x;
    const int gn = b * NN + n;
    const float x1 = xyz1[(size_t)gn * 3 + 0];
    const float y1 = xyz1[(size_t)gn * 3 + 1];
    const float z1 = xyz1[(size_t)gn * 3 + 2];
    const float n1 = x1 * x1 + y1 * y1 + z1 * z1;

    float d0 = 3.4e38f, d1 = 3.4e38f, d2 = 3.4e38f;
    int   i0 = 0, i1 = 0, i2 = 0;

    #pragma unroll 4
    for (int s = 0; s < SS; s++) {
        float4 p = sh[s];
        float dot = x1 * p.x + y1 * p.y + z1 * p.z;
        float d = (n1 + p.w) - 2.0f * dot;
        if (d < d2) {
            if (d < d1) {
                d2 = d1; i2 = i1;
                if (d < d0) { d1 = d0; i1 = i0; d0 = d; i0 = s; }
                else        { d1 = d;  i1 = s; }
            } else { d2 = d; i2 = s; }
        }
    }

    const float rw0 = rel_w[0], rw1 = rel_w[1], rw2 = rel_w[2], rw3 = rel_w[3];
    const float rb  = rel_b[0];
    int   is[3] = { i0, i1, i2 };
    float ds[3] = { d0, d1, d2 };
    #pragma unroll
    for (int k = 0; k < 3; k++) {
        float4 p = sh[is[k]];
        float ox = x1 - p.x, oy = y1 - p.y, oz = z1 - p.z;
        float zl = ds[k] * rw0 + ox * rw1 + oy * rw2 + oz * rw3 + rb;
        float w = 1.0f / (1.0f + expf(-zl));
        g_idx[gn * 3 + k] = is[k];
        g_w[gn * 3 + k]   = w * (1.0f / 3.0f);
    }
}

// ---------------------------------------------------------------------------
// GEMM0 with fused interp/concat on A. Tile 64x256, 256 threads, 2 CTAs/SM.
// R9 configuration (best measured: 150.7us). LDT=36, 2-stage, LDS.32 frags.
// ---------------------------------------------------------------------------
__global__ __launch_bounds__(256, 2)
void gemm0_kernel(const float* __restrict__ points1,
                  const float* __restrict__ points2,
                  const float* __restrict__ Bw,
                  const float* __restrict__ bias, float* __restrict__ C,
                  double* __restrict__ Sum, double* __restrict__ Ss) {
    constexpr int KT    = K0;             // 512
    constexpr int NT    = H0;             // 256
    constexpr int TM    = 64;
    constexpr int NC    = KT / 32;        // 16
    constexpr int LDT   = 36;
    constexpr int STAGE = (TM + NT) * LDT;

    extern __shared__ float sm[];
    const uint32_t smb = smem_u32(sm);

    const int tid    = threadIdx.x;
    const int wid    = tid >> 5;
    const int lane   = tid & 31;
    const int g      = lane >> 2;
    const int tg     = lane & 3;
    const int warp_m = wid >> 2;          // 0..1
    const int warp_n = wid & 3;           // 0..3
    const size_t bm  = (size_t)blockIdx.x * TM;

    // A staging: row lr (0..63), col group lq*8
    const int lr = tid >> 2;
    const int lq = tid & 3;
    const int gn = (int)bm + lr;
    const float* p2b = points2 + (size_t)(gn >> 13) * SS * DD;
    const int   j0 = g_idx[gn * 3 + 0], j1 = g_idx[gn * 3 + 1], j2 = g_idx[gn * 3 + 2];
    const float w0 = g_w[gn * 3 + 0],  w1 = g_w[gn * 3 + 1],  w2 = g_w[gn * 3 + 2];
    const float* r0 = p2b + (size_t)j0 * DD;
    const float* r1 = p2b + (size_t)j1 * DD;
    const float* r2 = p2b + (size_t)j2 * DD;
    const float* q  = points1 + (size_t)gn * DD;

    float acc[2][8][4];
    #pragma unroll
    for (int mt = 0; mt < 2; mt++)
        #pragma unroll
        for (int nt = 0; nt < 8; nt++)
            #pragma unroll
            for (int i = 0; i < 4; i++) acc[mt][nt][i] = 0.0f;

    auto load_a_regs = [&](int kt, float4* av) {
        if (kt < 8) {
            const float* P = q + kt * 32 + lq * 8;
            av[0] = *(const float4*)P;
            av[1] = *(const float4*)(P + 4);
        } else {
            const int cc = (kt - 8) * 32 + lq * 8;
            av[0] = *(const float4*)(r0 + cc);
            av[1] = *(const float4*)(r0 + cc + 4);
            av[2] = *(const float4*)(r1 + cc);
            av[3] = *(const float4*)(r1 + cc + 4);
            av[4] = *(const float4*)(r2 + cc);
            av[5] = *(const float4*)(r2 + cc + 4);
        }
    };
    auto store_a = [&](int kt, int s, const float4* av) {
        float* dst = sm + s * STAGE + lr * LDT + lq * 8;
        if (kt < 8) {
            #pragma unroll
            for (int i = 0; i < 2; i++) {
                float4 v;
                v.x = f2tf32f(av[i].x); v.y = f2tf32f(av[i].y);
                v.z = f2tf32f(av[i].z); v.w = f2tf32f(av[i].w);
                *(float4*)(dst + 4 * i) = v;
            }
        } else {
            #pragma unroll
            for (int i = 0; i < 2; i++) {
                float4 a = av[i], b = av[2 + i], c = av[4 + i];
                float4 v;
                v.x = f2tf32f(fmaf(a.x, w0, fmaf(b.x, w1, c.x * w2)));
                v.y = f2tf32f(fmaf(a.y, w0, fmaf(b.y, w1, c.y * w2)));
                v.z = f2tf32f(fmaf(a.z, w0, fmaf(b.z, w1, c.z * w2)));
                v.w = f2tf32f(fmaf(a.w, w0, fmaf(b.w, w1, c.w * w2)));
                *(float4*)(dst + 4 * i) = v;
            }
        }
    };
    auto load_b_stage = [&](int kt, int s) {
        const float* Bg = Bw + kt * 32;
        const uint32_t base = smb + (uint32_t)(s * STAGE + TM * LDT) * 4u;
        #pragma unroll
        for (int i = 0; i < 8; i++) {
            int id = i * 256 + tid;
            int r = id >> 3, kk = (id & 7) * 4;
            CP_ASYNC16(base + (r * LDT + kk) * 4, Bg + (size_t)r * KT + kk);
        }
        CP_COMMIT();
    };

    // prologue: stage 0
    {
        float4 av[6];
        load_a_regs(0, av);
        load_b_stage(0, 0);
        store_a(0, 0, av);
    }

    for (int kt = 0; kt < NC; kt++) {
        CP_WAIT(0);          // B(kt) landed
        __syncthreads();     // stage kt visible; buf (kt+1)&1 free

        float4 av[6];
        if (kt + 1 < NC) {
            load_a_regs(kt + 1, av);          // LDG overlaps compute(kt)
            load_b_stage(kt + 1, (kt + 1) & 1);
        }

        const uint32_t* as = (const uint32_t*)sm + (kt & 1) * STAGE + (warp_m * 32) * LDT;
        const uint32_t* bs = (const uint32_t*)sm + (kt & 1) * STAGE + TM * LDT
                           + (warp_n * 64) * LDT;

        #pragma unroll
        for (int kc = 0; kc < 4; kc++) {
            uint32_t a[2][4];
            #pragma unroll
            for (int mt = 0; mt < 2; mt++) {
                int base = (mt * 16 + g) * LDT + kc * 8 + tg;
                a[mt][0] = as[base];
                a[mt][1] = as[base + 8 * LDT];
                a[mt][2] = as[base + 4];
                a[mt][3] = as[base + 8 * LDT + 4];
            }
            #pragma unroll
            for (int nt = 0; nt < 8; nt++) {
                int bb = (nt * 8 + g) * LDT + kc * 8 + tg;
                uint32_t b[2] = { bs[bb], bs[bb + 4] };
                mma_tf32_16x8x8(acc[0][nt], a[0], b);
                mma_tf32_16x8x8(acc[1][nt], a[1], b);
            }
        }

        if (kt + 1 < NC) store_a(kt + 1, (kt + 1) & 1, av);
    }

    // stats partials (smem reuse)
    __syncthreads();
    if (tid < NT) { sm[tid] = 0.0f; sm[NT + tid] = 0.0f; }
    __syncthreads();

    #pragma unroll
    for (int nt = 0; nt < 8; nt++) {
        int col = warp_n * 64 + nt * 8 + 2 * tg;
        float bi0 = __ldg(&bias[col]), bi1 = __ldg(&bias[col + 1]);
        float s0 = 0.f, s1 = 0.f, q0 = 0.f, q1 = 0.f;
        #pragma unroll
        for (int mt = 0; mt < 2; mt++) {
            size_t r = bm + warp_m * 32 + mt * 16 + g;
            float v0x = acc[mt][nt][0] + bi0, v0y = acc[mt][nt][1] + bi1;
            float v1x = acc[mt][nt][2] + bi0, v1y = acc[mt][nt][3] + bi1;
            *(float2*)(C + r * NT + col)       = make_float2(v0x, v0y);
            *(float2*)(C + (r + 8) * NT + col) = make_float2(v1x, v1y);
            s0 += v0x + v1x;  s1 += v0y + v1y;
            q0 += v0x * v0x + v1x * v1x;
            q1 += v0y * v0y + v1y * v1y;
        }
        #pragma unroll
        for (int d = 4; d < 32; d <<= 1) {
            s0 += __shfl_xor_sync(0xffffffffu, s0, d);
            s1 += __shfl_xor_sync(0xffffffffu, s1, d);
            q0 += __shfl_xor_sync(0xffffffffu, q0, d);
            q1 += __shfl_xor_sync(0xffffffffu, q1, d);
        }
        if (lane < 4) {
            int c = warp_n * 64 + nt * 8 + 2 * lane;
            atomicAdd(&sm[c],          s0);
            atomicAdd(&sm[c + 1],      s1);
            atomicAdd(&sm[NT + c],     q0);
            atomicAdd(&sm[NT + c + 1], q1);
        }
    }
    __syncthreads();
    if (tid < NT) {
        atomicAdd(&Sum[tid], (double)sm[tid]);
        atomicAdd(&Ss[tid],  (double)sm[NT + tid]);
    }
}

// ---------------------------------------------------------------------------
// GEMM1: out = relu(s0*Y0 + t0) @ W1^T + b1, fused BN on A + fused stats.
// BN0 finalize computed per-CTA into static smem (identical formula).
// 128x128 tile, 3-stage pipeline (CP_WAIT(1)), 2 CTAs/SM.
// ---------------------------------------------------------------------------
__global__ __launch_bounds__(256, 2)
void gemm1_kernel(const float* __restrict__ A, const float* __restrict__ Bw,
                  const float* __restrict__ bias,
                  const double* __restrict__ Sum0, const double* __restrict__ Ss0,
                  const float* __restrict__ gamma0, const float* __restrict__ beta0,
                  float* __restrict__ C,
                  double* __restrict__ Sum, double* __restrict__ Ss) {
    constexpr int KT    = H0;             // 256
    constexpr int NT    = H1;             // 128
    constexpr int NC    = KT / 32;        // 8
    constexpr int LDT   = 36;
    constexpr int STAGE = 2 * 128 * LDT;  // A rows then B rows

    extern __shared__ float sm[];
    __shared__ float s_sc[H0], s_shf[H0];
    const uint32_t smb = smem_u32(sm);

    const int tid    = threadIdx.x;
    const int wid    = tid >> 5;
    const int lane   = tid & 31;
    const int g      = lane >> 2;
    const int tg     = lane & 3;
    const int warp_m = wid >> 1;
    const int warp_n = wid & 1;
    const size_t bm  = (size_t)blockIdx.x * 128;

    const int lr = tid >> 1;
    const int lk = (tid & 1) * 16;

    // per-CTA BN0 finalize (identical formula to the old finalize_kernel)
    {
        double mean = Sum0[tid] * (1.0 / (double)MM);
        double var  = Ss0[tid]  * (1.0 / (double)MM) - mean * mean;
        float s = gamma0[tid] * rsqrtf((float)var + BNEPS);
        s_sc[tid]  = s;
        s_shf[tid] = beta0[tid] - (float)mean * s;
    }

    float acc[2][8][4];
    #pragma unroll
    for (int mt = 0; mt < 2; mt++)
        #pragma unroll
        for (int nt = 0; nt < 8; nt++)
            #pragma unroll
            for (int i = 0; i < 4; i++) acc[mt][nt][i] = 0.0f;

    auto load_a_regs = [&](int kt, float4* av) {
        const float* Ag = A + (size_t)(bm + lr) * KT + kt * 32 + lk;
        #pragma unroll
        for (int i = 0; i < 4; i++) av[i] = *(const float4*)(Ag + 4 * i);
    };
    auto store_a = [&](int kt, int s, const float4* av) {
        const int c0 = kt * 32 + lk;
        float* dst = sm + s * STAGE + lr * LDT + lk;
        #pragma unroll
        for (int i = 0; i < 4; i++) {
            float4 s4 = *(const float4*)(s_sc  + c0 + 4 * i);
            float4 t4 = *(const float4*)(s_shf + c0 + 4 * i);
            float4 v;
            v.x = f2tf32f(fmaxf(0.0f, fmaf(av[i].x, s4.x, t4.x)));
            v.y = f2tf32f(fmaxf(0.0f, fmaf(av[i].y, s4.y, t4.y)));
            v.z = f2tf32f(fmaxf(0.0f, fmaf(av[i].z, s4.z, t4.z)));
            v.w = f2tf32f(fmaxf(0.0f, fmaf(av[i].w, s4.w, t4.w)));
            *(float4*)(dst + 4 * i) = v;
        }
    };
    auto load_b_stage = [&](int kt, int s) {
        const float* Bg = Bw + kt * 32;
        const uint32_t base = smb + (uint32_t)(s * STAGE + 128 * LDT) * 4u;
        #pragma unroll
        for (int i = 0; i < 4; i++) {
            int id = i * 256 + tid;
            int r = id >> 3, kk = (id & 7) * 4;
            CP_ASYNC16(base + (r * LDT + kk) * 4, Bg + (size_t)r * KT + kk);
        }
        CP_COMMIT();
    };

    // prologue: stages 0 and 1 (store_a only after s_sc/s_shf are published)
    {
        float4 av0[4], av1[4];
        load_b_stage(0, 0);
        load_a_regs(0, av0);
        load_b_stage(1, 1);
        load_a_regs(1, av1);
        __syncthreads();               // s_sc/s_shf visible to all threads
        store_a(0, 0, av0);
        store_a(1, 1, av1);
    }

    for (int kt = 0; kt < NC; kt++) {
        if (kt + 1 < NC) { CP_WAIT(1); } else { CP_WAIT(0); }
        __syncthreads();     // stage kt%3 visible; stage (kt+2)%3 free

        float4 av[4];
        if (kt + 2 < NC) {
            load_a_regs(kt + 2, av);
            load_b_stage(kt + 2, (kt + 2) % 3);
        }

        const uint32_t* as = (const uint32_t*)sm + (kt % 3) * STAGE + (warp_m * 32) * LDT;
        const uint32_t* bs = (const uint32_t*)sm + (kt % 3) * STAGE + 128 * LDT
                           + (warp_n * 64) * LDT;

        #pragma unroll
        for (int kc = 0; kc < 4; kc++) {
            uint32_t a[2][4];
            #pragma unroll
            for (int mt = 0; mt < 2; mt++) {
                int base = (mt * 16 + g) * LDT + kc * 8 + tg;
                a[mt][0] = as[base];
                a[mt][1] = as[base + 8 * LDT];
                a[mt][2] = as[base + 4];
                a[mt][3] = as[base + 8 * LDT + 4];
            }
            #pragma unroll
            for (int nt = 0; nt < 8; nt++) {
                int bb = (nt * 8 + g) * LDT + kc * 8 + tg;
                uint32_t b[2] = { bs[bb], bs[bb + 4] };
                mma_tf32_16x8x8(acc[0][nt], a[0], b);
                mma_tf32_16x8x8(acc[1][nt], a[1], b);
            }
        }

        if (kt + 2 < NC) store_a(kt + 2, (kt + 2) % 3, av);
    }

    __syncthreads();
    if (tid < NT) { sm[tid] = 0.0f; sm[NT + tid] = 0.0f; }
    __syncthreads();

    #pragma unroll
    for (int nt = 0; nt < 8; nt++) {
        int col = warp_n * 64 + nt * 8 + 2 * tg;
        float bi0 = __ldg(&bias[col]), bi1 = __ldg(&bias[col + 1]);
        float s0 = 0.f, s1 = 0.f, q0 = 0.f, q1 = 0.f;
        #pragma unroll
        for (int mt = 0; mt < 2; mt++) {
            size_t r = bm + warp_m * 32 + mt * 16 + g;
            float v0x = acc[mt][nt][0] + bi0, v0y = acc[mt][nt][1] + bi1;
            float v1x = acc[mt][nt][2] + bi0, v1y = acc[mt][nt][3] + bi1;
            *(float2*)(C + r * NT + col)       = make_float2(v0x, v0y);
            *(float2*)(C + (r + 8) * NT + col) = make_float2(v1x, v1y);
            s0 += v0x + v1x;  s1 += v0y + v1y;
            q0 += v0x * v0x + v1x * v1x;
            q1 += v0y * v0y + v1y * v1y;
        }
        #pragma unroll
        for (int d = 4; d < 32; d <<= 1) {
            s0 += __shfl_xor_sync(0xffffffffu, s0, d);
            s1 += __shfl_xor_sync(0xffffffffu, s1, d);
            q0 += __shfl_xor_sync(0xffffffffu, q0, d);
            q1 += __shfl_xor_sync(0xffffffffu, q1, d);
        }
        if (lane < 4) {
            int c = warp_n * 64 + nt * 8 + 2 * lane;
            atomicAdd(&sm[c],          s0);
            atomicAdd(&sm[c + 1],      s1);
            atomicAdd(&sm[NT + c],     q0);
            atomicAdd(&sm[NT + c + 1], q1);
        }
    }
    __syncthreads();
    if (tid < NT) {
        atomicAdd(&Sum[tid], (double)sm[tid]);
        atomicAdd(&Ss[tid],  (double)sm[NT + tid]);
    }
}

// ---------------------------------------------------------------------------
// act: per-block BN1 finalize + BN+ReLU in place. 4 float4 per thread
// (grid 2048) so the per-block finalize overhead is amortized 16x.
// ---------------------------------------------------------------------------
__global__ void act_kernel(float* __restrict__ Y,
                           const double* __restrict__ Sum1,
                           const double* __restrict__ Ss1,
                           const float* __restrict__ gamma1,
                           const float* __restrict__ beta1) {
    __shared__ float s_sc[H1], s_shf[H1];
    int t = threadIdx.x;
    if (t < H1) {
        double mean = Sum1[t] * (1.0 / (double)MM);
        double var  = Ss1[t]  * (1.0 / (double)MM) - mean * mean;
        float s = gamma1[t] * rsqrtf((float)var + BNEPS);
        s_sc[t]  = s;
        s_shf[t] = beta1[t] - (float)mean * s;
    }
    __syncthreads();

    int base = blockIdx.x * 1024 + threadIdx.x;   // float4 index
    #pragma unroll
    for (int j = 0; j < 4; j++) {
        int i = base + j * 256;
        float4 v = ((float4*)Y)[i];
        const float4 s4 = *(const float4*)(s_sc  + (i & 31) * 4);
        const float4 t4 = *(const float4*)(s_shf + (i & 31) * 4);
        v.x = fmaxf(0.0f, fmaf(v.x, s4.x, t4.x));
        v.y = fmaxf(0.0f, fmaf(v.y, s4.y, t4.y));
        v.z = fmaxf(0.0f, fmaf(v.z, s4.z, t4.z));
        v.w = fmaxf(0.0f, fmaf(v.w, s4.w, t4.w));
        ((float4*)Y)[i] = v;
    }
}

// ---------------------------------------------------------------------------
// Launch sequence: prep(1), knn(2), gemm0(3), gemm1(4), act(5)
// ---------------------------------------------------------------------------
extern "C" void kernel_launch(void* const* d_in, const int* in_sizes, int n_in,
                              void* d_out, int out_size) {
    const float* xyz1    = (const float*)d_in[0];
    const float* xyz2    = (const float*)d_in[1];
    const float* points1 = (const float*)d_in[2];
    const float* points2 = (const float*)d_in[3];
    const float* rel_w   = (const float*)d_in[4];
    const float* rel_b   = (const float*)d_in[5];
    const float* W0      = (const float*)d_in[6];
    const float* b0      = (const float*)d_in[7];
    const float* g0      = (const float*)d_in[8];
    const float* be0     = (const float*)d_in[9];
    const float* W1      = (const float*)d_in[10];
    const float* b1      = (const float*)d_in[11];
    const float* g1      = (const float*)d_in[12];
    const float* be1     = (const float*)d_in[13];
    float* out = (float*)d_out;

    float *p_y0, *p_w0t, *p_w1t;
    double *p_sum0, *p_ss0, *p_sum1, *p_ss1;
    cudaGetSymbolAddress((void**)&p_y0,   g_y0);
    cudaGetSymbolAddress((void**)&p_w0t,  g_w0t);
    cudaGetSymbolAddress((void**)&p_w1t,  g_w1t);
    cudaGetSymbolAddress((void**)&p_sum0, g_sum0);
    cudaGetSymbolAddress((void**)&p_ss0,  g_ss0);
    cudaGetSymbolAddress((void**)&p_sum1, g_sum1);
    cudaGetSymbolAddress((void**)&p_ss1,  g_ss1);

    const int smem0 = (64 + H0) * 36 * 4 * 2;     // 92160 B (2 stages)
    const int smem1 = 3 * 2 * 128 * 36 * 4;       // 110592 B (3 stages)
    cudaFuncSetAttribute(gemm0_kernel,
                         cudaFuncAttributeMaxDynamicSharedMemorySize, smem0);
    cudaFuncSetAttribute(gemm1_kernel,
                         cudaFuncAttributeMaxDynamicSharedMemorySize, smem1);

    prep_kernel<<<(H0 * K0 + 255) / 256, 256>>>(W0, W1);
    knn_kernel<<<dim3(NN / 128, BB), 128>>>(xyz1, xyz2, rel_w, rel_b);

    gemm0_kernel<<<MM / 64, 256, smem0>>>(points1, points2, p_w0t, b0,
                                          p_y0, p_sum0, p_ss0);

    gemm1_kernel<<<MM / 128, 256, smem1>>>(p_y0, p_w1t, b1,
                                           p_sum0, p_ss0, g0, be0,
                                           out, p_sum1, p_ss1);

    act_kernel<<<(MM * H1 / 4) / 1024, 256>>>(out, p_sum1, p_ss1, g1, be1);
}

// round 17
// speedup vs baseline: 1.1963x; 1.0610x over previous
#include <cuda_runtime.h>
#include <math.h>
#include <stdint.h>

// Problem constants
#define BB   8
#define NN   8192
#define SS   2048
#define DD   256
#define MM   65536      // BB*NN
#define H0   256
#define H1   128
#define K0   512        // 2*DD
#define BNEPS 1e-5f
#define SH   (SS / 2)   // candidates per KNN half-block

// ---------------------------------------------------------------------------
// Scratch
// ---------------------------------------------------------------------------
__device__ float  g_y0 [(size_t)MM * H0];   // layer0 pre-BN output (fp32)
__device__ float  g_w0t[H0 * K0];           // W0 as tf32 bits
__device__ float  g_w1t[H1 * H0];           // W1 as tf32 bits
__device__ int    g_idx[MM * 3];
__device__ float  g_w  [MM * 3];
__device__ float  g_hd [2][MM * 3];         // per-half top-3 distances
__device__ int    g_hi [2][MM * 3];         // per-half top-3 indices (global s)
__device__ double g_sum0[H0], g_ss0[H0], g_sum1[H1], g_ss1[H1];

// ---------------------------------------------------------------------------
// Portable PTX helpers
// ---------------------------------------------------------------------------
__device__ __forceinline__ uint32_t smem_u32(const void* p) {
    uint32_t a;
    asm("{ .reg .u64 t; cvta.to.shared.u64 t, %1; cvt.u32.u64 %0, t; }" : "=r"(a) : "l"(p));
    return a;
}

#define CP_ASYNC16(dst, src) \
    asm volatile("cp.async.cg.shared.global [%0], [%1], 16;" :: "r"(dst), "l"(src) : "memory")
#define CP_COMMIT() asm volatile("cp.async.commit_group;" ::: "memory")
#define CP_WAIT(n)  asm volatile("cp.async.wait_group %0;" :: "n"(n) : "memory")

__device__ __forceinline__ float f2tf32f(float x) {
    uint32_t r;
    asm("cvt.rna.tf32.f32 %0, %1;" : "=r"(r) : "f"(x));
    return __uint_as_float(r);
}

__device__ __forceinline__ void mma_tf32_16x8x8(float* c, const uint32_t* a,
                                                const uint32_t* b) {
    asm volatile(
        "mma.sync.aligned.m16n8k8.row.col.f32.tf32.tf32.f32 "
        "{%0,%1,%2,%3}, {%4,%5,%6,%7}, {%8,%9}, {%0,%1,%2,%3};"
        : "+f"(c[0]), "+f"(c[1]), "+f"(c[2]), "+f"(c[3])
        : "r"(a[0]), "r"(a[1]), "r"(a[2]), "r"(a[3]), "r"(b[0]), "r"(b[1]));
}

// ---------------------------------------------------------------------------
// prep: zero stats (block 0) + convert W0/W1 to tf32 bits
// ---------------------------------------------------------------------------
__global__ void prep_kernel(const float* __restrict__ W0,
                            const float* __restrict__ W1) {
    int i = blockIdx.x * blockDim.x + threadIdx.x;
    if (blockIdx.x == 0) {
        int t = threadIdx.x;
        if (t < H0) { g_sum0[t] = 0.0; g_ss0[t] = 0.0; }
        if (t < H1) { g_sum1[t] = 0.0; g_ss1[t] = 0.0; }
    }
    if (i < H0 * K0) g_w0t[i] = f2tf32f(W0[i]);
    if (i < H1 * H0) g_w1t[i] = f2tf32f(W1[i]);
}

// ---------------------------------------------------------------------------
// KNN half-scan: grid (NN/128, BB, 2). Each block scans its 1024-candidate
// half with the identical distance expression and stable top-3 insertion.
// Sequential strict-< top-3 == lexicographic (d, idx) top-3 of the half.
// ---------------------------------------------------------------------------
__global__ void knn_half_kernel(const float* __restrict__ xyz1,
                                const float* __restrict__ xyz2) {
    __shared__ float4 sh[SH];
    const int b = blockIdx.y;
    const int h = blockIdx.z;
    const float* x2 = xyz2 + ((size_t)b * SS + h * SH) * 3;
    for (int s = threadIdx.x; s < SH; s += 128) {
        float x = x2[s * 3 + 0], y = x2[s * 3 + 1], z = x2[s * 3 + 2];
        sh[s] = make_float4(x, y, z, x * x + y * y + z * z);
    }
    __syncthreads();

    const int n  = blockIdx.x * 128 + threadIdx.x;
    const int gn = b * NN + n;
    const float x1 = xyz1[(size_t)gn * 3 + 0];
    const float y1 = xyz1[(size_t)gn * 3 + 1];
    const float z1 = xyz1[(size_t)gn * 3 + 2];
    const float n1 = x1 * x1 + y1 * y1 + z1 * z1;

    float d0 = 3.4e38f, d1 = 3.4e38f, d2 = 3.4e38f;
    int   i0 = 0, i1 = 0, i2 = 0;

    #pragma unroll 4
    for (int s = 0; s < SH; s++) {
        float4 p = sh[s];
        float dot = x1 * p.x + y1 * p.y + z1 * p.z;
        float d = (n1 + p.w) - 2.0f * dot;
        if (d < d2) {
            if (d < d1) {
                d2 = d1; i2 = i1;
                if (d < d0) { d1 = d0; i1 = i0; d0 = d; i0 = s; }
                else        { d1 = d;  i1 = s; }
            } else { d2 = d; i2 = s; }
        }
    }

    const int base = h * SH;
    g_hd[h][gn * 3 + 0] = d0;  g_hi[h][gn * 3 + 0] = base + i0;
    g_hd[h][gn * 3 + 1] = d1;  g_hi[h][gn * 3 + 1] = base + i1;
    g_hd[h][gn * 3 + 2] = d2;  g_hi[h][gn * 3 + 2] = base + i2;
}

// ---------------------------------------------------------------------------
// KNN merge + weights: merge the two sorted 3-lists lexicographically by
// (d, idx) — exactly reproduces the single sequential scan's selection —
// then compute the sigmoid weights with the identical formula.
// ---------------------------------------------------------------------------
__global__ void knn_merge_kernel(const float* __restrict__ xyz1,
                                 const float* __restrict__ xyz2,
                                 const float* __restrict__ rel_w,
                                 const float* __restrict__ rel_b) {
    const int gn = blockIdx.x * 256 + threadIdx.x;
    const int b  = gn >> 13;

    float ld[3], rd[3];
    int   li[3], ri[3];
    #pragma unroll
    for (int k = 0; k < 3; k++) {
        ld[k] = g_hd[0][gn * 3 + k];  li[k] = g_hi[0][gn * 3 + k];
        rd[k] = g_hd[1][gn * 3 + k];  ri[k] = g_hi[1][gn * 3 + k];
    }

    float ds[3]; int is[3];
    int a = 0, c = 0;
    #pragma unroll
    for (int k = 0; k < 3; k++) {
        bool takeL = (a < 3) && (c >= 3 || ld[a] < rd[c]
                                 || (ld[a] == rd[c] && li[a] < ri[c]));
        if (takeL) { ds[k] = ld[a]; is[k] = li[a]; a++; }
        else       { ds[k] = rd[c]; is[k] = ri[c]; c++; }
    }

    const float x1 = xyz1[(size_t)gn * 3 + 0];
    const float y1 = xyz1[(size_t)gn * 3 + 1];
    const float z1 = xyz1[(size_t)gn * 3 + 2];
    const float rw0 = rel_w[0], rw1 = rel_w[1], rw2 = rel_w[2], rw3 = rel_w[3];
    const float rb  = rel_b[0];
    const float* x2 = xyz2 + (size_t)b * SS * 3;

    #pragma unroll
    for (int k = 0; k < 3; k++) {
        const float* p = x2 + (size_t)is[k] * 3;
        float ox = x1 - p[0], oy = y1 - p[1], oz = z1 - p[2];
        float zl = ds[k] * rw0 + ox * rw1 + oy * rw2 + oz * rw3 + rb;
        float w = 1.0f / (1.0f + expf(-zl));
        g_idx[gn * 3 + k] = is[k];
        g_w[gn * 3 + k]   = w * (1.0f / 3.0f);
    }
}

// ---------------------------------------------------------------------------
// GEMM0 with fused interp/concat on A. Tile 64x256, 256 threads, 2 CTAs/SM.
// R9 configuration (best measured: 150.7us). LDT=36, 2-stage, LDS.32 frags.
// ---------------------------------------------------------------------------
__global__ __launch_bounds__(256, 2)
void gemm0_kernel(const float* __restrict__ points1,
                  const float* __restrict__ points2,
                  const float* __restrict__ Bw,
                  const float* __restrict__ bias, float* __restrict__ C,
                  double* __restrict__ Sum, double* __restrict__ Ss) {
    constexpr int KT    = K0;             // 512
    constexpr int NT    = H0;             // 256
    constexpr int TM    = 64;
    constexpr int NC    = KT / 32;        // 16
    constexpr int LDT   = 36;
    constexpr int STAGE = (TM + NT) * LDT;

    extern __shared__ float sm[];
    const uint32_t smb = smem_u32(sm);

    const int tid    = threadIdx.x;
    const int wid    = tid >> 5;
    const int lane   = tid & 31;
    const int g      = lane >> 2;
    const int tg     = lane & 3;
    const int warp_m = wid >> 2;          // 0..1
    const int warp_n = wid & 3;           // 0..3
    const size_t bm  = (size_t)blockIdx.x * TM;

    // A staging: row lr (0..63), col group lq*8
    const int lr = tid >> 2;
    const int lq = tid & 3;
    const int gn = (int)bm + lr;
    const float* p2b = points2 + (size_t)(gn >> 13) * SS * DD;
    const int   j0 = g_idx[gn * 3 + 0], j1 = g_idx[gn * 3 + 1], j2 = g_idx[gn * 3 + 2];
    const float w0 = g_w[gn * 3 + 0],  w1 = g_w[gn * 3 + 1],  w2 = g_w[gn * 3 + 2];
    const float* r0 = p2b + (size_t)j0 * DD;
    const float* r1 = p2b + (size_t)j1 * DD;
    const float* r2 = p2b + (size_t)j2 * DD;
    const float* q  = points1 + (size_t)gn * DD;

    float acc[2][8][4];
    #pragma unroll
    for (int mt = 0; mt < 2; mt++)
        #pragma unroll
        for (int nt = 0; nt < 8; nt++)
            #pragma unroll
            for (int i = 0; i < 4; i++) acc[mt][nt][i] = 0.0f;

    auto load_a_regs = [&](int kt, float4* av) {
        if (kt < 8) {
            const float* P = q + kt * 32 + lq * 8;
            av[0] = *(const float4*)P;
            av[1] = *(const float4*)(P + 4);
        } else {
            const int cc = (kt - 8) * 32 + lq * 8;
            av[0] = *(const float4*)(r0 + cc);
            av[1] = *(const float4*)(r0 + cc + 4);
            av[2] = *(const float4*)(r1 + cc);
            av[3] = *(const float4*)(r1 + cc + 4);
            av[4] = *(const float4*)(r2 + cc);
            av[5] = *(const float4*)(r2 + cc + 4);
        }
    };
    auto store_a = [&](int kt, int s, const float4* av) {
        float* dst = sm + s * STAGE + lr * LDT + lq * 8;
        if (kt < 8) {
            #pragma unroll
            for (int i = 0; i < 2; i++) {
                float4 v;
                v.x = f2tf32f(av[i].x); v.y = f2tf32f(av[i].y);
                v.z = f2tf32f(av[i].z); v.w = f2tf32f(av[i].w);
                *(float4*)(dst + 4 * i) = v;
            }
        } else {
            #pragma unroll
            for (int i = 0; i < 2; i++) {
                float4 a = av[i], b = av[2 + i], c = av[4 + i];
                float4 v;
                v.x = f2tf32f(fmaf(a.x, w0, fmaf(b.x, w1, c.x * w2)));
                v.y = f2tf32f(fmaf(a.y, w0, fmaf(b.y, w1, c.y * w2)));
                v.z = f2tf32f(fmaf(a.z, w0, fmaf(b.z, w1, c.z * w2)));
                v.w = f2tf32f(fmaf(a.w, w0, fmaf(b.w, w1, c.w * w2)));
                *(float4*)(dst + 4 * i) = v;
            }
        }
    };
    auto load_b_stage = [&](int kt, int s) {
        const float* Bg = Bw + kt * 32;
        const uint32_t base = smb + (uint32_t)(s * STAGE + TM * LDT) * 4u;
        #pragma unroll
        for (int i = 0; i < 8; i++) {
            int id = i * 256 + tid;
            int r = id >> 3, kk = (id & 7) * 4;
            CP_ASYNC16(base + (r * LDT + kk) * 4, Bg + (size_t)r * KT + kk);
        }
        CP_COMMIT();
    };

    // prologue: stage 0
    {
        float4 av[6];
        load_a_regs(0, av);
        load_b_stage(0, 0);
        store_a(0, 0, av);
    }

    for (int kt = 0; kt < NC; kt++) {
        CP_WAIT(0);          // B(kt) landed
        __syncthreads();     // stage kt visible; buf (kt+1)&1 free

        float4 av[6];
        if (kt + 1 < NC) {
            load_a_regs(kt + 1, av);          // LDG overlaps compute(kt)
            load_b_stage(kt + 1, (kt + 1) & 1);
        }

        const uint32_t* as = (const uint32_t*)sm + (kt & 1) * STAGE + (warp_m * 32) * LDT;
        const uint32_t* bs = (const uint32_t*)sm + (kt & 1) * STAGE + TM * LDT
                           + (warp_n * 64) * LDT;

        #pragma unroll
        for (int kc = 0; kc < 4; kc++) {
            uint32_t a[2][4];
            #pragma unroll
            for (int mt = 0; mt < 2; mt++) {
                int base = (mt * 16 + g) * LDT + kc * 8 + tg;
                a[mt][0] = as[base];
                a[mt][1] = as[base + 8 * LDT];
                a[mt][2] = as[base + 4];
                a[mt][3] = as[base + 8 * LDT + 4];
            }
            #pragma unroll
            for (int nt = 0; nt < 8; nt++) {
                int bb = (nt * 8 + g) * LDT + kc * 8 + tg;
                uint32_t b[2] = { bs[bb], bs[bb + 4] };
                mma_tf32_16x8x8(acc[0][nt], a[0], b);
                mma_tf32_16x8x8(acc[1][nt], a[1], b);
            }
        }

        if (kt + 1 < NC) store_a(kt + 1, (kt + 1) & 1, av);
    }

    // stats partials (smem reuse)
    __syncthreads();
    if (tid < NT) { sm[tid] = 0.0f; sm[NT + tid] = 0.0f; }
    __syncthreads();

    #pragma unroll
    for (int nt = 0; nt < 8; nt++) {
        int col = warp_n * 64 + nt * 8 + 2 * tg;
        float bi0 = __ldg(&bias[col]), bi1 = __ldg(&bias[col + 1]);
        float s0 = 0.f, s1 = 0.f, q0 = 0.f, q1 = 0.f;
        #pragma unroll
        for (int mt = 0; mt < 2; mt++) {
            size_t r = bm + warp_m * 32 + mt * 16 + g;
            float v0x = acc[mt][nt][0] + bi0, v0y = acc[mt][nt][1] + bi1;
            float v1x = acc[mt][nt][2] + bi0, v1y = acc[mt][nt][3] + bi1;
            *(float2*)(C + r * NT + col)       = make_float2(v0x, v0y);
            *(float2*)(C + (r + 8) * NT + col) = make_float2(v1x, v1y);
            s0 += v0x + v1x;  s1 += v0y + v1y;
            q0 += v0x * v0x + v1x * v1x;
            q1 += v0y * v0y + v1y * v1y;
        }
        #pragma unroll
        for (int d = 4; d < 32; d <<= 1) {
            s0 += __shfl_xor_sync(0xffffffffu, s0, d);
            s1 += __shfl_xor_sync(0xffffffffu, s1, d);
            q0 += __shfl_xor_sync(0xffffffffu, q0, d);
            q1 += __shfl_xor_sync(0xffffffffu, q1, d);
        }
        if (lane < 4) {
            int c = warp_n * 64 + nt * 8 + 2 * lane;
            atomicAdd(&sm[c],          s0);
            atomicAdd(&sm[c + 1],      s1);
            atomicAdd(&sm[NT + c],     q0);
            atomicAdd(&sm[NT + c + 1], q1);
        }
    }
    __syncthreads();
    if (tid < NT) {
        atomicAdd(&Sum[tid], (double)sm[tid]);
        atomicAdd(&Ss[tid],  (double)sm[NT + tid]);
    }
}

// ---------------------------------------------------------------------------
// GEMM1: out = relu(s0*Y0 + t0) @ W1^T + b1, fused BN on A + fused stats.
// BN0 finalize computed per-CTA into static smem (identical formula).
// 128x128 tile, 3-stage pipeline (CP_WAIT(1)), 2 CTAs/SM.
// ---------------------------------------------------------------------------
__global__ __launch_bounds__(256, 2)
void gemm1_kernel(const float* __restrict__ A, const float* __restrict__ Bw,
                  const float* __restrict__ bias,
                  const double* __restrict__ Sum0, const double* __restrict__ Ss0,
                  const float* __restrict__ gamma0, const float* __restrict__ beta0,
                  float* __restrict__ C,
                  double* __restrict__ Sum, double* __restrict__ Ss) {
    constexpr int KT    = H0;             // 256
    constexpr int NT    = H1;             // 128
    constexpr int NC    = KT / 32;        // 8
    constexpr int LDT   = 36;
    constexpr int STAGE = 2 * 128 * LDT;  // A rows then B rows

    extern __shared__ float sm[];
    __shared__ float s_sc[H0], s_shf[H0];
    const uint32_t smb = smem_u32(sm);

    const int tid    = threadIdx.x;
    const int wid    = tid >> 5;
    const int lane   = tid & 31;
    const int g      = lane >> 2;
    const int tg     = lane & 3;
    const int warp_m = wid >> 1;
    const int warp_n = wid & 1;
    const size_t bm  = (size_t)blockIdx.x * 128;

    const int lr = tid >> 1;
    const int lk = (tid & 1) * 16;

    // per-CTA BN0 finalize (identical formula to the old finalize_kernel)
    {
        double mean = Sum0[tid] * (1.0 / (double)MM);
        double var  = Ss0[tid]  * (1.0 / (double)MM) - mean * mean;
        float s = gamma0[tid] * rsqrtf((float)var + BNEPS);
        s_sc[tid]  = s;
        s_shf[tid] = beta0[tid] - (float)mean * s;
    }

    float acc[2][8][4];
    #pragma unroll
    for (int mt = 0; mt < 2; mt++)
        #pragma unroll
        for (int nt = 0; nt < 8; nt++)
            #pragma unroll
            for (int i = 0; i < 4; i++) acc[mt][nt][i] = 0.0f;

    auto load_a_regs = [&](int kt, float4* av) {
        const float* Ag = A + (size_t)(bm + lr) * KT + kt * 32 + lk;
        #pragma unroll
        for (int i = 0; i < 4; i++) av[i] = *(const float4*)(Ag + 4 * i);
    };
    auto store_a = [&](int kt, int s, const float4* av) {
        const int c0 = kt * 32 + lk;
        float* dst = sm + s * STAGE + lr * LDT + lk;
        #pragma unroll
        for (int i = 0; i < 4; i++) {
            float4 s4 = *(const float4*)(s_sc  + c0 + 4 * i);
            float4 t4 = *(const float4*)(s_shf + c0 + 4 * i);
            float4 v;
            v.x = f2tf32f(fmaxf(0.0f, fmaf(av[i].x, s4.x, t4.x)));
            v.y = f2tf32f(fmaxf(0.0f, fmaf(av[i].y, s4.y, t4.y)));
            v.z = f2tf32f(fmaxf(0.0f, fmaf(av[i].z, s4.z, t4.z)));
            v.w = f2tf32f(fmaxf(0.0f, fmaf(av[i].w, s4.w, t4.w)));
            *(float4*)(dst + 4 * i) = v;
        }
    };
    auto load_b_stage = [&](int kt, int s) {
        const float* Bg = Bw + kt * 32;
        const uint32_t base = smb + (uint32_t)(s * STAGE + 128 * LDT) * 4u;
        #pragma unroll
        for (int i = 0; i < 4; i++) {
            int id = i * 256 + tid;
            int r = id >> 3, kk = (id & 7) * 4;
            CP_ASYNC16(base + (r * LDT + kk) * 4, Bg + (size_t)r * KT + kk);
        }
        CP_COMMIT();
    };

    // prologue: stages 0 and 1 (store_a only after s_sc/s_shf are published)
    {
        float4 av0[4], av1[4];
        load_b_stage(0, 0);
        load_a_regs(0, av0);
        load_b_stage(1, 1);
        load_a_regs(1, av1);
        __syncthreads();               // s_sc/s_shf visible to all threads
        store_a(0, 0, av0);
        store_a(1, 1, av1);
    }

    for (int kt = 0; kt < NC; kt++) {
        if (kt + 1 < NC) { CP_WAIT(1); } else { CP_WAIT(0); }
        __syncthreads();     // stage kt%3 visible; stage (kt+2)%3 free

        float4 av[4];
        if (kt + 2 < NC) {
            load_a_regs(kt + 2, av);
            load_b_stage(kt + 2, (kt + 2) % 3);
        }

        const uint32_t* as = (const uint32_t*)sm + (kt % 3) * STAGE + (warp_m * 32) * LDT;
        const uint32_t* bs = (const uint32_t*)sm + (kt % 3) * STAGE + 128 * LDT
                           + (warp_n * 64) * LDT;

        #pragma unroll
        for (int kc = 0; kc < 4; kc++) {
            uint32_t a[2][4];
            #pragma unroll
            for (int mt = 0; mt < 2; mt++) {
                int base = (mt * 16 + g) * LDT + kc * 8 + tg;
                a[mt][0] = as[base];
                a[mt][1] = as[base + 8 * LDT];
                a[mt][2] = as[base + 4];
                a[mt][3] = as[base + 8 * LDT + 4];
            }
            #pragma unroll
            for (int nt = 0; nt < 8; nt++) {
                int bb = (nt * 8 + g) * LDT + kc * 8 + tg;
                uint32_t b[2] = { bs[bb], bs[bb + 4] };
                mma_tf32_16x8x8(acc[0][nt], a[0], b);
                mma_tf32_16x8x8(acc[1][nt], a[1], b);
            }
        }

        if (kt + 2 < NC) store_a(kt + 2, (kt + 2) % 3, av);
    }

    __syncthreads();
    if (tid < NT) { sm[tid] = 0.0f; sm[NT + tid] = 0.0f; }
    __syncthreads();

    #pragma unroll
    for (int nt = 0; nt < 8; nt++) {
        int col = warp_n * 64 + nt * 8 + 2 * tg;
        float bi0 = __ldg(&bias[col]), bi1 = __ldg(&bias[col + 1]);
        float s0 = 0.f, s1 = 0.f, q0 = 0.f, q1 = 0.f;
        #pragma unroll
        for (int mt = 0; mt < 2; mt++) {
            size_t r = bm + warp_m * 32 + mt * 16 + g;
            float v0x = acc[mt][nt][0] + bi0, v0y = acc[mt][nt][1] + bi1;
            float v1x = acc[mt][nt][2] + bi0, v1y = acc[mt][nt][3] + bi1;
            *(float2*)(C + r * NT + col)       = make_float2(v0x, v0y);
            *(float2*)(C + (r + 8) * NT + col) = make_float2(v1x, v1y);
            s0 += v0x + v1x;  s1 += v0y + v1y;
            q0 += v0x * v0x + v1x * v1x;
            q1 += v0y * v0y + v1y * v1y;
        }
        #pragma unroll
        for (int d = 4; d < 32; d <<= 1) {
            s0 += __shfl_xor_sync(0xffffffffu, s0, d);
            s1 += __shfl_xor_sync(0xffffffffu, s1, d);
            q0 += __shfl_xor_sync(0xffffffffu, q0, d);
            q1 += __shfl_xor_sync(0xffffffffu, q1, d);
        }
        if (lane < 4) {
            int c = warp_n * 64 + nt * 8 + 2 * lane;
            atomicAdd(&sm[c],          s0);
            atomicAdd(&sm[c + 1],      s1);
            atomicAdd(&sm[NT + c],     q0);
            atomicAdd(&sm[NT + c + 1], q1);
        }
    }
    __syncthreads();
    if (tid < NT) {
        atomicAdd(&Sum[tid], (double)sm[tid]);
        atomicAdd(&Ss[tid],  (double)sm[NT + tid]);
    }
}

// ---------------------------------------------------------------------------
// act: per-block BN1 finalize + BN+ReLU in place. 4 float4 per thread.
// ---------------------------------------------------------------------------
__global__ void act_kernel(float* __restrict__ Y,
                           const double* __restrict__ Sum1,
                           const double* __restrict__ Ss1,
                           const float* __restrict__ gamma1,
                           const float* __restrict__ beta1) {
    __shared__ float s_sc[H1], s_shf[H1];
    int t = threadIdx.x;
    if (t < H1) {
        double mean = Sum1[t] * (1.0 / (double)MM);
        double var  = Ss1[t]  * (1.0 / (double)MM) - mean * mean;
        float s = gamma1[t] * rsqrtf((float)var + BNEPS);
        s_sc[t]  = s;
        s_shf[t] = beta1[t] - (float)mean * s;
    }
    __syncthreads();

    int base = blockIdx.x * 1024 + threadIdx.x;   // float4 index
    #pragma unroll
    for (int j = 0; j < 4; j++) {
        int i = base + j * 256;
        float4 v = ((float4*)Y)[i];
        const float4 s4 = *(const float4*)(s_sc  + (i & 31) * 4);
        const float4 t4 = *(const float4*)(s_shf + (i & 31) * 4);
        v.x = fmaxf(0.0f, fmaf(v.x, s4.x, t4.x));
        v.y = fmaxf(0.0f, fmaf(v.y, s4.y, t4.y));
        v.z = fmaxf(0.0f, fmaf(v.z, s4.z, t4.z));
        v.w = fmaxf(0.0f, fmaf(v.w, s4.w, t4.w));
        ((float4*)Y)[i] = v;
    }
}

// ---------------------------------------------------------------------------
// Launch sequence
// ---------------------------------------------------------------------------
extern "C" void kernel_launch(void* const* d_in, const int* in_sizes, int n_in,
                              void* d_out, int out_size) {
    const float* xyz1    = (const float*)d_in[0];
    const float* xyz2    = (const float*)d_in[1];
    const float* points1 = (const float*)d_in[2];
    const float* points2 = (const float*)d_in[3];
    const float* rel_w   = (const float*)d_in[4];
    const float* rel_b   = (const float*)d_in[5];
    const float* W0      = (const float*)d_in[6];
    const float* b0      = (const float*)d_in[7];
    const float* g0      = (const float*)d_in[8];
    const float* be0     = (const float*)d_in[9];
    const float* W1      = (const float*)d_in[10];
    const float* b1      = (const float*)d_in[11];
    const float* g1      = (const float*)d_in[12];
    const float* be1     = (const float*)d_in[13];
    float* out = (float*)d_out;

    float *p_y0, *p_w0t, *p_w1t;
    double *p_sum0, *p_ss0, *p_sum1, *p_ss1;
    cudaGetSymbolAddress((void**)&p_y0,   g_y0);
    cudaGetSymbolAddress((void**)&p_w0t,  g_w0t);
    cudaGetSymbolAddress((void**)&p_w1t,  g_w1t);
    cudaGetSymbolAddress((void**)&p_sum0, g_sum0);
    cudaGetSymbolAddress((void**)&p_ss0,  g_ss0);
    cudaGetSymbolAddress((void**)&p_sum1, g_sum1);
    cudaGetSymbolAddress((void**)&p_ss1,  g_ss1);

    const int smem0 = (64 + H0) * 36 * 4 * 2;     // 92160 B (2 stages)
    const int smem1 = 3 * 2 * 128 * 36 * 4;       // 110592 B (3 stages)
    cudaFuncSetAttribute(gemm0_kernel,
                         cudaFuncAttributeMaxDynamicSharedMemorySize, smem0);
    cudaFuncSetAttribute(gemm1_kernel,
                         cudaFuncAttributeMaxDynamicSharedMemorySize, smem1);

    prep_kernel<<<(H0 * K0 + 255) / 256, 256>>>(W0, W1);
    knn_half_kernel<<<dim3(NN / 128, BB, 2), 128>>>(xyz1, xyz2);
    knn_merge_kernel<<<MM / 256, 256>>>(xyz1, xyz2, rel_w, rel_b);

    gemm0_kernel<<<MM / 64, 256, smem0>>>(points1, points2, p_w0t, b0,
                                          p_y0, p_sum0, p_ss0);

    gemm1_kernel<<<MM / 128, 256, smem1>>>(p_y0, p_w1t, b1,
                                           p_sum0, p_ss0, g0, be0,
                                           out, p_sum1, p_ss1);

    act_kernel<<<(MM * H1 / 4) / 1024, 256>>>(out, p_sum1, p_ss1, g1, be1);
}